// round 16
// baseline (speedup 1.0000x reference)
#include <cuda_runtime.h>
#include <cuda_fp16.h>
#include <cstdint>

// Problem constants
#define B_ 4
#define T_ 2048
#define C_ 1024
#define H_ 16
#define D_ 64
#define BT_ (B_ * T_)            // 8192
#define KDIM 1024

#define QSCALE 0.18033688011112042f   // 0.125 * log2(e)

// ---------------------------------------------------------------------------
// Scratch (device globals). ALL operands single-term fp16.
// ---------------------------------------------------------------------------
__device__ __half g_x[(size_t)BT_ * KDIM];     // x fp16 [B,T,C]
__device__ __half g_w[(size_t)3 * C_ * KDIM];  // W_attn^T [3072][1024]
__device__ __half g_p[(size_t)C_ * KDIM];      // W_proj^T [1024][1024]
__device__ __half g_a[(size_t)BT_ * KDIM];     // attn-out fp16 [B,T,C]
// Q (pre-scaled by QSCALE), K, V fp16 in [B,H,T,D]
__device__ __half g_q[(size_t)BT_ * C_];
__device__ __half g_k[(size_t)BT_ * C_];
__device__ __half g_v[(size_t)BT_ * C_];

// ---------------------------------------------------------------------------
// helpers (sm_80-era PTX — legal at compute_103 base)
// ---------------------------------------------------------------------------
__device__ __forceinline__ uint32_t s2u(const void* p) {
    uint32_t a;
    asm("{ .reg .u64 t; cvta.to.shared.u64 t, %1; cvt.u32.u64 %0, t; }" : "=r"(a) : "l"(p));
    return a;
}
__device__ __forceinline__ uint32_t swz(uint32_t off) {   // SW128
    return off ^ ((off >> 3) & 0x70);
}
__device__ __forceinline__ void cp_async16(uint32_t dst, const void* src) {
    asm volatile("cp.async.cg.shared.global [%0], [%1], 16;" :: "r"(dst), "l"(src) : "memory");
}
__device__ __forceinline__ void ldsm4(uint32_t* r, uint32_t addr) {
    asm volatile("ldmatrix.sync.aligned.m8n8.x4.shared.b16 {%0,%1,%2,%3}, [%4];"
                 : "=r"(r[0]), "=r"(r[1]), "=r"(r[2]), "=r"(r[3]) : "r"(addr));
}
__device__ __forceinline__ void ldsm4t(uint32_t* r, uint32_t addr) {
    asm volatile("ldmatrix.sync.aligned.m8n8.x4.trans.shared.b16 {%0,%1,%2,%3}, [%4];"
                 : "=r"(r[0]), "=r"(r[1]), "=r"(r[2]), "=r"(r[3]) : "r"(addr));
}
__device__ __forceinline__ void mma2(float* c, const uint32_t* a, uint32_t b0, uint32_t b1) {
    asm volatile(
        "mma.sync.aligned.m16n8k16.row.col.f32.f16.f16.f32 "
        "{%0,%1,%2,%3}, {%4,%5,%6,%7}, {%8,%9}, {%0,%1,%2,%3};"
        : "+f"(c[0]), "+f"(c[1]), "+f"(c[2]), "+f"(c[3])
        : "r"(a[0]), "r"(a[1]), "r"(a[2]), "r"(a[3]), "r"(b0), "r"(b1));
}
__device__ __forceinline__ uint32_t packh2(float x, float y) {
    __half2 t; t.x = __float2half(x); t.y = __float2half(y);
    return *(uint32_t*)&t;
}
// exp2 of two floats -> packed half2 {lo=exp2(a), hi=exp2(b)} via one MUFU op.
__device__ __forceinline__ uint32_t exp2_h2(float a, float b) {
    uint32_t t;
    asm("cvt.rn.f16x2.f32 %0, %2, %1;" : "=r"(t) : "f"(a), "f"(b));  // hi=b, lo=a
    asm("ex2.approx.f16x2 %0, %0;" : "+r"(t));
    return t;
}
__device__ __forceinline__ float qred_max(float v) {
    v = fmaxf(v, __shfl_xor_sync(~0u, v, 1));
    return fmaxf(v, __shfl_xor_sync(~0u, v, 2));
}
__device__ __forceinline__ float qred_sum(float v) {
    v += __shfl_xor_sync(~0u, v, 1);
    return v + __shfl_xor_sync(~0u, v, 2);
}

// ---------------------------------------------------------------------------
// Fused conversion kernel (one launch).
// ---------------------------------------------------------------------------
__global__ __launch_bounds__(256)
void convert_all(const float* __restrict__ x,
                 const float* __restrict__ Wattn,
                 const float* __restrict__ Wproj)
{
    const int blk = blockIdx.x;
    if (blk < 1024) {
        const size_t n4 = (size_t)BT_ * KDIM / 4;
        for (size_t i = (size_t)blk * 256 + threadIdx.x; i < n4; i += (size_t)1024 * 256) {
            float4 v = ((const float4*)x)[i];
            ((uint32_t*)g_x)[2 * i]     = packh2(v.x, v.y);
            ((uint32_t*)g_x)[2 * i + 1] = packh2(v.z, v.w);
        }
    } else {
        const int W = (blk < 4096) ? 0 : 1;
        const int bidx = W ? (blk - 4096) : (blk - 1024);
        const int NBX = W ? 32 : 96;
        const int NC = W ? C_ : 3 * C_;
        const float* src = W ? Wproj : Wattn;
        __half* dh = W ? g_p : g_w;
        const int bx = bidx % NBX;
        const int by = bidx / NBX;
        const int tx = threadIdx.x & 31;
        const int ty = threadIdx.x >> 5;
        __shared__ float tile[32][33];
        const int xcol = bx * 32 + tx;
        const int y0 = by * 32;
#pragma unroll
        for (int j = 0; j < 32; j += 8)
            tile[ty + j][tx] = src[(size_t)(y0 + ty + j) * NC + xcol];
        __syncthreads();
        const int ox = y0 + tx;
        const int oyb = bx * 32;
#pragma unroll
        for (int j = 0; j < 32; j += 8)
            dh[(size_t)(oyb + ty + j) * KDIM + ox] = __float2half(tile[tx][ty + j]);
    }
}

// ---------------------------------------------------------------------------
// Plain fp16 GEMM, now PERSISTENT: grid = 296 CTAs (2/SM), each loops over
// tiles (perfect load balance; no ragged tail wave). Per tile: CTA 128x128,
// 4 warps x 64x64, K_chunk=64, 3-stage ring, one sync/chunk.
// MODE 0: NTILES=1536 (24 x 64), MODE 1: NTILES=512 (8 x 64).
// ---------------------------------------------------------------------------
#define SM_STAGE 32768
#define SMEM_GEMM_BYTES 98304    // 3 stages
#define NCH 16                   // 1024 / 64
#define GPERS 296                // 148 SMs x 2 CTAs

template <int MODE>
__global__ __launch_bounds__(128, 2)
void mma_gemm(const float* __restrict__ bias,
              float* __restrict__ o0, float* __restrict__ o1, float* __restrict__ o2)
{
    extern __shared__ __align__(1024) char smem[];
    const uint32_t sm = s2u(smem);
    const int tid = threadIdx.x;
    const int wid = tid >> 5;
    const int lid = tid & 31;

    constexpr int NBX = (MODE == 0) ? 24 : 8;
    constexpr int NTILES = NBX * 64;

    const __half* Ap = (MODE == 0) ? g_x : g_a;
    const __half* Bp = (MODE == 0) ? g_w : g_p;

    const int wm = (wid & 1) * 64;
    const int wn = (wid >> 1) * 64;
    const int g = lid >> 2;
    const int tig = lid & 3;
    const int aRow = lid & 15;
    const int aKb = (lid >> 4) * 16;
    const int bRow = ((lid >> 4) & 1) * 8 + (lid & 7);
    const int bKb = ((lid >> 3) & 1) * 16;

    for (int tile = blockIdx.x; tile < NTILES; tile += GPERS) {
        const int n0 = (tile % NBX) * 128;
        const int m0 = (tile / NBX) * 128;

        auto issue_loads = [&](int c, int s) {
            const uint32_t sb = sm + (uint32_t)s * SM_STAGE;
#pragma unroll
            for (int r = 0; r < 16; r++) {
                const int id = tid + r * 128;
                const int row = (id >> 3) & 127;
                const int c16 = id & 7;
                const uint32_t off = swz((uint32_t)(row * 128 + c16 * 16));
                if (id < 1024)
                    cp_async16(sb + off, Ap + (size_t)(m0 + row) * KDIM + c * 64 + c16 * 8);
                else
                    cp_async16(sb + 16384 + off, Bp + (size_t)(n0 + row) * KDIM + c * 64 + c16 * 8);
            }
            asm volatile("cp.async.commit_group;" ::: "memory");
        };

        float Cr[4][8][4];
#pragma unroll
        for (int mi = 0; mi < 4; mi++)
#pragma unroll
            for (int j = 0; j < 8; j++)
#pragma unroll
                for (int qi = 0; qi < 4; qi++) Cr[mi][j][qi] = 0.f;

        issue_loads(0, 0);
        issue_loads(1, 1);

        for (int c = 0; c < NCH; c++) {
            const int s = c % 3;
            if (c < NCH - 1) asm volatile("cp.async.wait_group 1;" ::: "memory");
            else             asm volatile("cp.async.wait_group 0;" ::: "memory");
            __syncthreads();
            if (c + 2 < NCH) issue_loads(c + 2, (c + 2) % 3);

            const uint32_t sb = sm + (uint32_t)s * SM_STAGE;
            const uint32_t tA = sb, tB = sb + 16384;

#pragma unroll
            for (int ks = 0; ks < 4; ks++) {
                const int kb = ks * 32;
                uint32_t af[4][4], bf[4][4];
#pragma unroll
                for (int mi = 0; mi < 4; mi++) {
                    const uint32_t off = swz((uint32_t)((wm + mi * 16 + aRow) * 128 + kb + aKb));
                    ldsm4(af[mi], tA + off);
                }
#pragma unroll
                for (int jp = 0; jp < 4; jp++) {
                    const uint32_t off = swz((uint32_t)((wn + jp * 16 + bRow) * 128 + kb + bKb));
                    ldsm4(bf[jp], tB + off);
                }
#pragma unroll
                for (int mi = 0; mi < 4; mi++)
#pragma unroll
                    for (int j = 0; j < 8; j++) {
                        const int jp = j >> 1, o = (j & 1) * 2;
                        mma2(Cr[mi][j], af[mi], bf[jp][o], bf[jp][o + 1]);
                    }
            }
        }
        __syncthreads();   // stage buffers reusable for next tile

        // ---- epilogue ----
#pragma unroll
        for (int mi = 0; mi < 4; mi++)
#pragma unroll
            for (int j = 0; j < 8; j++) {
                const int col = n0 + wn + (j >> 1) * 16 + (j & 1) * 8 + tig * 2;
                const float2 bb = *(const float2*)(bias + col);
#pragma unroll
                for (int half = 0; half < 2; half++) {
                    const int row = m0 + wm + mi * 16 + g + half * 8;
                    float2 v;
                    v.x = Cr[mi][j][half * 2 + 0] + bb.x;
                    v.y = Cr[mi][j][half * 2 + 1] + bb.y;
                    if (MODE == 0) {
                        const int seg = col >> 10;
                        const int c0 = col & 1023;
                        const int h = c0 >> 6;
                        const int dd = c0 & 63;
                        const int b = row >> 11;
                        const int t = row & (T_ - 1);
                        const size_t idx = ((size_t)(b * H_ + h) * T_ + t) * D_ + dd;
                        if (seg == 0) {
                            *(uint32_t*)&g_q[idx] = packh2(v.x * QSCALE, v.y * QSCALE);
                        } else if (seg == 1) {
                            *(float2*)&o1[idx] = v;
                            *(uint32_t*)&g_k[idx] = packh2(v.x, v.y);
                        } else {
                            *(float2*)&o2[idx] = v;
                            *(uint32_t*)&g_v[idx] = packh2(v.x, v.y);
                        }
                    } else {
                        *(float2*)&o0[(size_t)row * C_ + col] = v;
                    }
                }
            }
    }
}

// ---------------------------------------------------------------------------
// Flash attention (exact R14 structure): 4 warps x 32 q-rows, KV tile 64,
// 3-stage, 2 CTAs/SM, ex2.approx.f16x2 softmax (P pre-packed). No diagonal
// specialization (measured: any skip logic regresses).
// ---------------------------------------------------------------------------
#define AT_SMEM 65536            // Q 16K + 3 stages x 16K

__global__ __launch_bounds__(128, 2)
void attn_mma()
{
    extern __shared__ __align__(1024) char smem[];
    const uint32_t sm = s2u(smem);
    const int tid = threadIdx.x;
    const int wid = tid >> 5;
    const int lid = tid & 31;
    const int qb = 15 - blockIdx.x;          // heavy CTAs first
    const int bh = blockIdx.y;
    const size_t base_qkv = (size_t)bh * T_ * D_;
    const int nt = 2 * qb + 2;

    // Q loads (folded into group 0): 1024 x 16B, 8 per thread
#pragma unroll
    for (int r = 0; r < 8; r++) {
        const int id = tid + r * 128;
        const int row = id >> 3;
        const int c16 = id & 7;
        const uint32_t dst = sm + swz((uint32_t)(row * 128 + c16 * 16));
        const __half* src = g_q + base_qkv + (size_t)(qb * 128 + row) * D_ + c16 * 8;
        cp_async16(dst, src);
    }
    auto issue_kv = [&](int kt, int s) {
        const uint32_t sb = sm + 16384 + (uint32_t)s * 16384;
#pragma unroll
        for (int r = 0; r < 8; r++) {
            const int id = tid + r * 128;
            const int bsel = id >> 9;        // 0 K 1 V
            const int row = (id >> 3) & 63;
            const int c16 = id & 7;
            const uint32_t dst = sb + bsel * 8192 + swz((uint32_t)(row * 128 + c16 * 16));
            const __half* src = (bsel ? g_v : g_k) + base_qkv
                                + (size_t)(kt * 64 + row) * D_ + c16 * 8;
            cp_async16(dst, src);
        }
        asm volatile("cp.async.commit_group;" ::: "memory");
    };
    issue_kv(0, 0);
    issue_kv(1, 1);

    const int g = lid >> 2;
    const int t2 = (lid & 3) * 2;
    const int lrow16 = lid & 15;
    const int lhi = (lid >> 4) * 16;
    const int wq = wid * 32;                 // warp q origin

    uint32_t qh[2][4][4];
    float cfr[2][8][4], ofr[2][8][4];
    uint32_t pfr[2][8][2];                   // packed fp16 P pairs
    float mr[2][2], lr[2][2];
#pragma unroll
    for (int mi = 0; mi < 2; mi++) {
        mr[mi][0] = -1e30f; mr[mi][1] = -1e30f;
        lr[mi][0] = 0.f;    lr[mi][1] = 0.f;
#pragma unroll
        for (int j = 0; j < 8; j++)
#pragma unroll
            for (int qi = 0; qi < 4; qi++) ofr[mi][j][qi] = 0.f;
    }

    for (int kb = 0; kb < nt; kb++) {
        const int s = kb % 3;
        if (kb + 1 < nt) asm volatile("cp.async.wait_group 1;" ::: "memory");
        else             asm volatile("cp.async.wait_group 0;" ::: "memory");
        __syncthreads();
        if (kb + 2 < nt) issue_kv(kb + 2, (kb + 2) % 3);
        if (kb == 0) {
#pragma unroll
            for (int mi = 0; mi < 2; mi++)
#pragma unroll
                for (int kc = 0; kc < 4; kc++) {
                    const uint32_t off =
                        swz((uint32_t)((wq + mi * 16 + lrow16) * 128 + kc * 32 + lhi));
                    ldsm4(qh[mi][kc], sm + off);
                }
        }
        const uint32_t kvb = sm + 16384 + (uint32_t)s * 16384;

        // ---- S = Q K^T ----
#pragma unroll
        for (int mi = 0; mi < 2; mi++)
#pragma unroll
            for (int j = 0; j < 8; j++)
#pragma unroll
                for (int qi = 0; qi < 4; qi++) cfr[mi][j][qi] = 0.f;
#pragma unroll
        for (int kc = 0; kc < 4; kc++) {
            uint32_t kf[4][4];
#pragma unroll
            for (int jp = 0; jp < 4; jp++) {
                const uint32_t off = swz((uint32_t)((jp * 16 + lrow16) * 128 + kc * 32 + lhi));
                ldsm4(kf[jp], kvb + off);
            }
#pragma unroll
            for (int mi = 0; mi < 2; mi++)
#pragma unroll
                for (int jp = 0; jp < 4; jp++) {
                    mma2(cfr[mi][2 * jp],     qh[mi][kc], kf[jp][0], kf[jp][2]);
                    mma2(cfr[mi][2 * jp + 1], qh[mi][kc], kf[jp][1], kf[jp][3]);
                }
        }

        // ---- causal mask (diagonal tiles only) ----
        if (kb >= 2 * qb) {
            const int kv0 = kb * 64;
#pragma unroll
            for (int mi = 0; mi < 2; mi++) {
                const int qr = qb * 128 + wq + mi * 16 + g;
#pragma unroll
                for (int j = 0; j < 8; j++) {
                    const int col = kv0 + j * 8 + t2;
#pragma unroll
                    for (int qi = 0; qi < 4; qi++) {
                        const int row = qr + ((qi >> 1) << 3);
                        if (col + (qi & 1) > row) cfr[mi][j][qi] = -1e30f;
                    }
                }
            }
        }

        // ---- online softmax (log2 domain; f16x2 exp -> P pre-packed) ----
#pragma unroll
        for (int mi = 0; mi < 2; mi++) {
            float mx0 = -1e30f, mx1 = -1e30f;
#pragma unroll
            for (int j = 0; j < 8; j++) {
                mx0 = fmaxf(mx0, fmaxf(cfr[mi][j][0], cfr[mi][j][1]));
                mx1 = fmaxf(mx1, fmaxf(cfr[mi][j][2], cfr[mi][j][3]));
            }
            mx0 = qred_max(mx0);
            mx1 = qred_max(mx1);
            const float mn0 = fmaxf(mr[mi][0], mx0), mn1 = fmaxf(mr[mi][1], mx1);
            const float al0 = exp2f(mr[mi][0] - mn0), al1 = exp2f(mr[mi][1] - mn1);
            mr[mi][0] = mn0; mr[mi][1] = mn1;
            float s0 = 0.f, s1 = 0.f;
#pragma unroll
            for (int j = 0; j < 8; j++) {
                const uint32_t p01 = exp2_h2(cfr[mi][j][0] - mn0, cfr[mi][j][1] - mn0);
                const uint32_t p23 = exp2_h2(cfr[mi][j][2] - mn1, cfr[mi][j][3] - mn1);
                pfr[mi][j][0] = p01;
                pfr[mi][j][1] = p23;
                const float2 f01 = __half22float2(*(const __half2*)&p01);
                const float2 f23 = __half22float2(*(const __half2*)&p23);
                s0 += f01.x + f01.y;
                s1 += f23.x + f23.y;
            }
            s0 = qred_sum(s0);
            s1 = qred_sum(s1);
            lr[mi][0] = lr[mi][0] * al0 + s0;
            lr[mi][1] = lr[mi][1] * al1 + s1;
#pragma unroll
            for (int j = 0; j < 8; j++) {
                ofr[mi][j][0] *= al0; ofr[mi][j][1] *= al0;
                ofr[mi][j][2] *= al1; ofr[mi][j][3] *= al1;
            }
        }

        // ---- O += P V (P pre-packed; no branches) ----
#pragma unroll
        for (int kc = 0; kc < 4; kc++) {
            uint32_t ph[2][4];
#pragma unroll
            for (int mi = 0; mi < 2; mi++) {
                ph[mi][0] = pfr[mi][2 * kc][0];
                ph[mi][1] = pfr[mi][2 * kc][1];
                ph[mi][2] = pfr[mi][2 * kc + 1][0];
                ph[mi][3] = pfr[mi][2 * kc + 1][1];
            }
#pragma unroll
            for (int nc = 0; nc < 4; nc++) {
                uint32_t vf[4];
                const uint32_t off = swz((uint32_t)((kc * 16 + lrow16) * 128 + nc * 32 + lhi));
                ldsm4t(vf, kvb + 8192 + off);
#pragma unroll
                for (int mi = 0; mi < 2; mi++) {
                    mma2(ofr[mi][2 * nc],     ph[mi], vf[0], vf[1]);
                    mma2(ofr[mi][2 * nc + 1], ph[mi], vf[2], vf[3]);
                }
            }
        }
    }

    // ---- epilogue: write fp16 into [B,T,C] for proj GEMM ----
    const int b = bh >> 4, h = bh & 15;
#pragma unroll
    for (int mi = 0; mi < 2; mi++) {
        const float inv0 = 1.f / lr[mi][0], inv1 = 1.f / lr[mi][1];
        const int t0 = qb * 128 + wq + mi * 16 + g;
#pragma unroll
        for (int j = 0; j < 8; j++) {
            const int d = j * 8 + t2;
            const size_t i0 = ((size_t)(b * T_ + t0)) * C_ + h * 64 + d;
            const size_t i1 = i0 + (size_t)8 * C_;
            *(uint32_t*)&g_a[i0] = packh2(ofr[mi][j][0] * inv0, ofr[mi][j][1] * inv0);
            *(uint32_t*)&g_a[i1] = packh2(ofr[mi][j][2] * inv1, ofr[mi][j][3] * inv1);
        }
    }
}

// ---------------------------------------------------------------------------
// Launch. Inputs: x, mask, W_attn, b_attn, W_proj, b_proj.
// Output: [out (B,T,C) | k (B,H,T,D) | v (B,H,T,D)] fp32.
// ---------------------------------------------------------------------------
extern "C" void kernel_launch(void* const* d_in, const int* in_sizes, int n_in,
                              void* d_out, int out_size)
{
    (void)in_sizes; (void)n_in; (void)out_size;
    const float* x      = (const float*)d_in[0];
    const float* W_attn = (const float*)d_in[2];
    const float* b_attn = (const float*)d_in[3];
    const float* W_proj = (const float*)d_in[4];
    const float* b_proj = (const float*)d_in[5];

    float* out  = (float*)d_out;
    float* kout = out + (size_t)B_ * H_ * T_ * D_;
    float* vout = kout + (size_t)B_ * H_ * T_ * D_;

    cudaFuncSetAttribute(mma_gemm<0>, cudaFuncAttributeMaxDynamicSharedMemorySize,
                         SMEM_GEMM_BYTES);
    cudaFuncSetAttribute(mma_gemm<1>, cudaFuncAttributeMaxDynamicSharedMemorySize,
                         SMEM_GEMM_BYTES);
    cudaFuncSetAttribute(attn_mma, cudaFuncAttributeMaxDynamicSharedMemorySize,
                         AT_SMEM);

    // 1) fused conversions
    convert_all<<<5120, 256>>>(x, W_attn, W_proj);

    // 2) QKV GEMM + bias + scatter (persistent, 296 CTAs over 1536 tiles)
    mma_gemm<0><<<GPERS, 128, SMEM_GEMM_BYTES>>>(b_attn, nullptr, kout, vout);

    // 3) causal flash attention -> g_a
    attn_mma<<<dim3(16, 64), 128, AT_SMEM>>>();

    // 4) proj GEMM (persistent, 296 CTAs over 512 tiles)
    mma_gemm<1><<<GPERS, 128, SMEM_GEMM_BYTES>>>(b_proj, out, nullptr, nullptr);
}

// round 17
// speedup vs baseline: 1.0383x; 1.0383x over previous
#include <cuda_runtime.h>
#include <cuda_fp16.h>
#include <cstdint>

// Problem constants
#define B_ 4
#define T_ 2048
#define C_ 1024
#define H_ 16
#define D_ 64
#define BT_ (B_ * T_)            // 8192
#define KDIM 1024

#define QSCALE 0.18033688011112042f   // 0.125 * log2(e)

// ---------------------------------------------------------------------------
// Scratch (device globals). ALL operands single-term fp16.
// ---------------------------------------------------------------------------
__device__ __half g_x[(size_t)BT_ * KDIM];     // x fp16 [B,T,C]
__device__ __half g_w[(size_t)3 * C_ * KDIM];  // W_attn^T [3072][1024]
__device__ __half g_p[(size_t)C_ * KDIM];      // W_proj^T [1024][1024]
__device__ __half g_a[(size_t)BT_ * KDIM];     // attn-out fp16 [B,T,C]
// Q (pre-scaled by QSCALE), K, V fp16 in [B,H,T,D]
__device__ __half g_q[(size_t)BT_ * C_];
__device__ __half g_k[(size_t)BT_ * C_];
__device__ __half g_v[(size_t)BT_ * C_];

// ---------------------------------------------------------------------------
// helpers (sm_80-era PTX — legal at compute_103 base)
// ---------------------------------------------------------------------------
__device__ __forceinline__ uint32_t s2u(const void* p) {
    uint32_t a;
    asm("{ .reg .u64 t; cvta.to.shared.u64 t, %1; cvt.u32.u64 %0, t; }" : "=r"(a) : "l"(p));
    return a;
}
__device__ __forceinline__ uint32_t swz(uint32_t off) {   // SW128
    return off ^ ((off >> 3) & 0x70);
}
__device__ __forceinline__ void cp_async16(uint32_t dst, const void* src) {
    asm volatile("cp.async.cg.shared.global [%0], [%1], 16;" :: "r"(dst), "l"(src) : "memory");
}
__device__ __forceinline__ void ldsm4(uint32_t* r, uint32_t addr) {
    asm volatile("ldmatrix.sync.aligned.m8n8.x4.shared.b16 {%0,%1,%2,%3}, [%4];"
                 : "=r"(r[0]), "=r"(r[1]), "=r"(r[2]), "=r"(r[3]) : "r"(addr));
}
__device__ __forceinline__ void ldsm4t(uint32_t* r, uint32_t addr) {
    asm volatile("ldmatrix.sync.aligned.m8n8.x4.trans.shared.b16 {%0,%1,%2,%3}, [%4];"
                 : "=r"(r[0]), "=r"(r[1]), "=r"(r[2]), "=r"(r[3]) : "r"(addr));
}
__device__ __forceinline__ void mma2(float* c, const uint32_t* a, uint32_t b0, uint32_t b1) {
    asm volatile(
        "mma.sync.aligned.m16n8k16.row.col.f32.f16.f16.f32 "
        "{%0,%1,%2,%3}, {%4,%5,%6,%7}, {%8,%9}, {%0,%1,%2,%3};"
        : "+f"(c[0]), "+f"(c[1]), "+f"(c[2]), "+f"(c[3])
        : "r"(a[0]), "r"(a[1]), "r"(a[2]), "r"(a[3]), "r"(b0), "r"(b1));
}
__device__ __forceinline__ uint32_t packh2(float x, float y) {
    __half2 t; t.x = __float2half(x); t.y = __float2half(y);
    return *(uint32_t*)&t;
}
// exp2 of two floats -> packed half2 {lo=exp2(a), hi=exp2(b)} via one MUFU op.
// Result is directly an fp16 P-fragment pair for mma.
__device__ __forceinline__ uint32_t exp2_h2(float a, float b) {
    uint32_t t;
    asm("cvt.rn.f16x2.f32 %0, %2, %1;" : "=r"(t) : "f"(a), "f"(b));  // hi=b, lo=a
    asm("ex2.approx.f16x2 %0, %0;" : "+r"(t));
    return t;
}
__device__ __forceinline__ float qred_max(float v) {
    v = fmaxf(v, __shfl_xor_sync(~0u, v, 1));
    return fmaxf(v, __shfl_xor_sync(~0u, v, 2));
}
__device__ __forceinline__ float qred_sum(float v) {
    v += __shfl_xor_sync(~0u, v, 1);
    return v + __shfl_xor_sync(~0u, v, 2);
}

// ---------------------------------------------------------------------------
// Fused conversion kernel (one launch).
// ---------------------------------------------------------------------------
__global__ __launch_bounds__(256)
void convert_all(const float* __restrict__ x,
                 const float* __restrict__ Wattn,
                 const float* __restrict__ Wproj)
{
    const int blk = blockIdx.x;
    if (blk < 1024) {
        const size_t n4 = (size_t)BT_ * KDIM / 4;
        for (size_t i = (size_t)blk * 256 + threadIdx.x; i < n4; i += (size_t)1024 * 256) {
            float4 v = ((const float4*)x)[i];
            ((uint32_t*)g_x)[2 * i]     = packh2(v.x, v.y);
            ((uint32_t*)g_x)[2 * i + 1] = packh2(v.z, v.w);
        }
    } else {
        const int W = (blk < 4096) ? 0 : 1;
        const int bidx = W ? (blk - 4096) : (blk - 1024);
        const int NBX = W ? 32 : 96;
        const int NC = W ? C_ : 3 * C_;
        const float* src = W ? Wproj : Wattn;
        __half* dh = W ? g_p : g_w;
        const int bx = bidx % NBX;
        const int by = bidx / NBX;
        const int tx = threadIdx.x & 31;
        const int ty = threadIdx.x >> 5;
        __shared__ float tile[32][33];
        const int xcol = bx * 32 + tx;
        const int y0 = by * 32;
#pragma unroll
        for (int j = 0; j < 32; j += 8)
            tile[ty + j][tx] = src[(size_t)(y0 + ty + j) * NC + xcol];
        __syncthreads();
        const int ox = y0 + tx;
        const int oyb = bx * 32;
#pragma unroll
        for (int j = 0; j < 32; j += 8)
            dh[(size_t)(oyb + ty + j) * KDIM + ox] = __float2half(tile[tx][ty + j]);
    }
}

// ---------------------------------------------------------------------------
// Plain fp16 GEMM (R12/R14 config — measured optimum): CTA 128x128,
// 4 warps x 64x64, K_chunk=64, 3-stage ring, one sync/chunk, 2 CTAs/SM.
// ---------------------------------------------------------------------------
#define SM_STAGE 32768
#define SMEM_GEMM_BYTES 98304    // 3 stages
#define NCH 16                   // 1024 / 64

template <int MODE>
__global__ __launch_bounds__(128, 2)
void mma_gemm(const float* __restrict__ bias,
              float* __restrict__ o0, float* __restrict__ o1, float* __restrict__ o2)
{
    extern __shared__ __align__(1024) char smem[];
    const uint32_t sm = s2u(smem);
    const int tid = threadIdx.x;
    const int wid = tid >> 5;
    const int lid = tid & 31;
    const int n0 = blockIdx.x * 128;
    const int m0 = blockIdx.y * 128;

    const __half* Ap = (MODE == 0) ? g_x : g_a;
    const __half* Bp = (MODE == 0) ? g_w : g_p;

    auto issue_loads = [&](int c, int s) {
        const uint32_t sb = sm + (uint32_t)s * SM_STAGE;
#pragma unroll
        for (int r = 0; r < 16; r++) {
            const int id = tid + r * 128;
            const int row = (id >> 3) & 127;
            const int c16 = id & 7;
            const uint32_t off = swz((uint32_t)(row * 128 + c16 * 16));
            if (id < 1024)
                cp_async16(sb + off, Ap + (size_t)(m0 + row) * KDIM + c * 64 + c16 * 8);
            else
                cp_async16(sb + 16384 + off, Bp + (size_t)(n0 + row) * KDIM + c * 64 + c16 * 8);
        }
        asm volatile("cp.async.commit_group;" ::: "memory");
    };

    const int wm = (wid & 1) * 64;
    const int wn = (wid >> 1) * 64;
    const int g = lid >> 2;
    const int tig = lid & 3;
    const int aRow = lid & 15;
    const int aKb = (lid >> 4) * 16;
    const int bRow = ((lid >> 4) & 1) * 8 + (lid & 7);
    const int bKb = ((lid >> 3) & 1) * 16;

    float Cr[4][8][4];
#pragma unroll
    for (int mi = 0; mi < 4; mi++)
#pragma unroll
        for (int j = 0; j < 8; j++)
#pragma unroll
            for (int qi = 0; qi < 4; qi++) Cr[mi][j][qi] = 0.f;

    issue_loads(0, 0);
    issue_loads(1, 1);

    for (int c = 0; c < NCH; c++) {
        const int s = c % 3;
        if (c < NCH - 1) asm volatile("cp.async.wait_group 1;" ::: "memory");
        else             asm volatile("cp.async.wait_group 0;" ::: "memory");
        __syncthreads();
        if (c + 2 < NCH) issue_loads(c + 2, (c + 2) % 3);

        const uint32_t sb = sm + (uint32_t)s * SM_STAGE;
        const uint32_t tA = sb, tB = sb + 16384;

#pragma unroll
        for (int ks = 0; ks < 4; ks++) {
            const int kb = ks * 32;
            uint32_t af[4][4], bf[4][4];
#pragma unroll
            for (int mi = 0; mi < 4; mi++) {
                const uint32_t off = swz((uint32_t)((wm + mi * 16 + aRow) * 128 + kb + aKb));
                ldsm4(af[mi], tA + off);
            }
#pragma unroll
            for (int jp = 0; jp < 4; jp++) {
                const uint32_t off = swz((uint32_t)((wn + jp * 16 + bRow) * 128 + kb + bKb));
                ldsm4(bf[jp], tB + off);
            }
#pragma unroll
            for (int mi = 0; mi < 4; mi++)
#pragma unroll
                for (int j = 0; j < 8; j++) {
                    const int jp = j >> 1, o = (j & 1) * 2;
                    mma2(Cr[mi][j], af[mi], bf[jp][o], bf[jp][o + 1]);
                }
        }
    }

    // ---- epilogue ----
#pragma unroll
    for (int mi = 0; mi < 4; mi++)
#pragma unroll
        for (int j = 0; j < 8; j++) {
            const int col = n0 + wn + (j >> 1) * 16 + (j & 1) * 8 + tig * 2;
            const float2 bb = *(const float2*)(bias + col);
#pragma unroll
            for (int half = 0; half < 2; half++) {
                const int row = m0 + wm + mi * 16 + g + half * 8;
                float2 v;
                v.x = Cr[mi][j][half * 2 + 0] + bb.x;
                v.y = Cr[mi][j][half * 2 + 1] + bb.y;
                if (MODE == 0) {
                    const int seg = col >> 10;
                    const int c0 = col & 1023;
                    const int h = c0 >> 6;
                    const int dd = c0 & 63;
                    const int b = row >> 11;
                    const int t = row & (T_ - 1);
                    const size_t idx = ((size_t)(b * H_ + h) * T_ + t) * D_ + dd;
                    if (seg == 0) {
                        *(uint32_t*)&g_q[idx] = packh2(v.x * QSCALE, v.y * QSCALE);
                    } else if (seg == 1) {
                        *(float2*)&o1[idx] = v;
                        *(uint32_t*)&g_k[idx] = packh2(v.x, v.y);
                    } else {
                        *(float2*)&o2[idx] = v;
                        *(uint32_t*)&g_v[idx] = packh2(v.x, v.y);
                    }
                } else {
                    *(float2*)&o0[(size_t)row * C_ + col] = v;
                }
            }
        }
}

// ---------------------------------------------------------------------------
// Flash attention (R14 — measured optimum): 4 warps x 32 q-rows, KV tile 64,
// 3-stage, 2 CTAs/SM, ex2.approx.f16x2 softmax (P pre-packed). No diagonal
// specialization (measured: any skip logic regresses).
// ---------------------------------------------------------------------------
#define AT_SMEM 65536            // Q 16K + 3 stages x 16K

__global__ __launch_bounds__(128, 2)
void attn_mma()
{
    extern __shared__ __align__(1024) char smem[];
    const uint32_t sm = s2u(smem);
    const int tid = threadIdx.x;
    const int wid = tid >> 5;
    const int lid = tid & 31;
    const int qb = 15 - blockIdx.x;          // heavy CTAs first
    const int bh = blockIdx.y;
    const size_t base_qkv = (size_t)bh * T_ * D_;
    const int nt = 2 * qb + 2;

    // Q loads (folded into group 0): 1024 x 16B, 8 per thread
#pragma unroll
    for (int r = 0; r < 8; r++) {
        const int id = tid + r * 128;
        const int row = id >> 3;
        const int c16 = id & 7;
        const uint32_t dst = sm + swz((uint32_t)(row * 128 + c16 * 16));
        const __half* src = g_q + base_qkv + (size_t)(qb * 128 + row) * D_ + c16 * 8;
        cp_async16(dst, src);
    }
    auto issue_kv = [&](int kt, int s) {
        const uint32_t sb = sm + 16384 + (uint32_t)s * 16384;
#pragma unroll
        for (int r = 0; r < 8; r++) {
            const int id = tid + r * 128;
            const int bsel = id >> 9;        // 0 K 1 V
            const int row = (id >> 3) & 63;
            const int c16 = id & 7;
            const uint32_t dst = sb + bsel * 8192 + swz((uint32_t)(row * 128 + c16 * 16));
            const __half* src = (bsel ? g_v : g_k) + base_qkv
                                + (size_t)(kt * 64 + row) * D_ + c16 * 8;
            cp_async16(dst, src);
        }
        asm volatile("cp.async.commit_group;" ::: "memory");
    };
    issue_kv(0, 0);
    issue_kv(1, 1);

    const int g = lid >> 2;
    const int t2 = (lid & 3) * 2;
    const int lrow16 = lid & 15;
    const int lhi = (lid >> 4) * 16;
    const int wq = wid * 32;                 // warp q origin

    uint32_t qh[2][4][4];
    float cfr[2][8][4], ofr[2][8][4];
    uint32_t pfr[2][8][2];                   // packed fp16 P pairs
    float mr[2][2], lr[2][2];
#pragma unroll
    for (int mi = 0; mi < 2; mi++) {
        mr[mi][0] = -1e30f; mr[mi][1] = -1e30f;
        lr[mi][0] = 0.f;    lr[mi][1] = 0.f;
#pragma unroll
        for (int j = 0; j < 8; j++)
#pragma unroll
            for (int qi = 0; qi < 4; qi++) ofr[mi][j][qi] = 0.f;
    }

    for (int kb = 0; kb < nt; kb++) {
        const int s = kb % 3;
        if (kb + 1 < nt) asm volatile("cp.async.wait_group 1;" ::: "memory");
        else             asm volatile("cp.async.wait_group 0;" ::: "memory");
        __syncthreads();
        if (kb + 2 < nt) issue_kv(kb + 2, (kb + 2) % 3);
        if (kb == 0) {
#pragma unroll
            for (int mi = 0; mi < 2; mi++)
#pragma unroll
                for (int kc = 0; kc < 4; kc++) {
                    const uint32_t off =
                        swz((uint32_t)((wq + mi * 16 + lrow16) * 128 + kc * 32 + lhi));
                    ldsm4(qh[mi][kc], sm + off);
                }
        }
        const uint32_t kvb = sm + 16384 + (uint32_t)s * 16384;

        // ---- S = Q K^T ----
#pragma unroll
        for (int mi = 0; mi < 2; mi++)
#pragma unroll
            for (int j = 0; j < 8; j++)
#pragma unroll
                for (int qi = 0; qi < 4; qi++) cfr[mi][j][qi] = 0.f;
#pragma unroll
        for (int kc = 0; kc < 4; kc++) {
            uint32_t kf[4][4];
#pragma unroll
            for (int jp = 0; jp < 4; jp++) {
                const uint32_t off = swz((uint32_t)((jp * 16 + lrow16) * 128 + kc * 32 + lhi));
                ldsm4(kf[jp], kvb + off);
            }
#pragma unroll
            for (int mi = 0; mi < 2; mi++)
#pragma unroll
                for (int jp = 0; jp < 4; jp++) {
                    mma2(cfr[mi][2 * jp],     qh[mi][kc], kf[jp][0], kf[jp][2]);
                    mma2(cfr[mi][2 * jp + 1], qh[mi][kc], kf[jp][1], kf[jp][3]);
                }
        }

        // ---- causal mask (diagonal tiles only) ----
        if (kb >= 2 * qb) {
            const int kv0 = kb * 64;
#pragma unroll
            for (int mi = 0; mi < 2; mi++) {
                const int qr = qb * 128 + wq + mi * 16 + g;
#pragma unroll
                for (int j = 0; j < 8; j++) {
                    const int col = kv0 + j * 8 + t2;
#pragma unroll
                    for (int qi = 0; qi < 4; qi++) {
                        const int row = qr + ((qi >> 1) << 3);
                        if (col + (qi & 1) > row) cfr[mi][j][qi] = -1e30f;
                    }
                }
            }
        }

        // ---- online softmax (log2 domain; f16x2 exp -> P pre-packed) ----
#pragma unroll
        for (int mi = 0; mi < 2; mi++) {
            float mx0 = -1e30f, mx1 = -1e30f;
#pragma unroll
            for (int j = 0; j < 8; j++) {
                mx0 = fmaxf(mx0, fmaxf(cfr[mi][j][0], cfr[mi][j][1]));
                mx1 = fmaxf(mx1, fmaxf(cfr[mi][j][2], cfr[mi][j][3]));
            }
            mx0 = qred_max(mx0);
            mx1 = qred_max(mx1);
            const float mn0 = fmaxf(mr[mi][0], mx0), mn1 = fmaxf(mr[mi][1], mx1);
            const float al0 = exp2f(mr[mi][0] - mn0), al1 = exp2f(mr[mi][1] - mn1);
            mr[mi][0] = mn0; mr[mi][1] = mn1;
            float s0 = 0.f, s1 = 0.f;
#pragma unroll
            for (int j = 0; j < 8; j++) {
                const uint32_t p01 = exp2_h2(cfr[mi][j][0] - mn0, cfr[mi][j][1] - mn0);
                const uint32_t p23 = exp2_h2(cfr[mi][j][2] - mn1, cfr[mi][j][3] - mn1);
                pfr[mi][j][0] = p01;
                pfr[mi][j][1] = p23;
                const float2 f01 = __half22float2(*(const __half2*)&p01);
                const float2 f23 = __half22float2(*(const __half2*)&p23);
                s0 += f01.x + f01.y;
                s1 += f23.x + f23.y;
            }
            s0 = qred_sum(s0);
            s1 = qred_sum(s1);
            lr[mi][0] = lr[mi][0] * al0 + s0;
            lr[mi][1] = lr[mi][1] * al1 + s1;
#pragma unroll
            for (int j = 0; j < 8; j++) {
                ofr[mi][j][0] *= al0; ofr[mi][j][1] *= al0;
                ofr[mi][j][2] *= al1; ofr[mi][j][3] *= al1;
            }
        }

        // ---- O += P V (P pre-packed; no branches) ----
#pragma unroll
        for (int kc = 0; kc < 4; kc++) {
            uint32_t ph[2][4];
#pragma unroll
            for (int mi = 0; mi < 2; mi++) {
                ph[mi][0] = pfr[mi][2 * kc][0];
                ph[mi][1] = pfr[mi][2 * kc][1];
                ph[mi][2] = pfr[mi][2 * kc + 1][0];
                ph[mi][3] = pfr[mi][2 * kc + 1][1];
            }
#pragma unroll
            for (int nc = 0; nc < 4; nc++) {
                uint32_t vf[4];
                const uint32_t off = swz((uint32_t)((kc * 16 + lrow16) * 128 + nc * 32 + lhi));
                ldsm4t(vf, kvb + 8192 + off);
#pragma unroll
                for (int mi = 0; mi < 2; mi++) {
                    mma2(ofr[mi][2 * nc],     ph[mi], vf[0], vf[1]);
                    mma2(ofr[mi][2 * nc + 1], ph[mi], vf[2], vf[3]);
                }
            }
        }
    }

    // ---- epilogue: write fp16 into [B,T,C] for proj GEMM ----
    const int b = bh >> 4, h = bh & 15;
#pragma unroll
    for (int mi = 0; mi < 2; mi++) {
        const float inv0 = 1.f / lr[mi][0], inv1 = 1.f / lr[mi][1];
        const int t0 = qb * 128 + wq + mi * 16 + g;
#pragma unroll
        for (int j = 0; j < 8; j++) {
            const int d = j * 8 + t2;
            const size_t i0 = ((size_t)(b * T_ + t0)) * C_ + h * 64 + d;
            const size_t i1 = i0 + (size_t)8 * C_;
            *(uint32_t*)&g_a[i0] = packh2(ofr[mi][j][0] * inv0, ofr[mi][j][1] * inv0);
            *(uint32_t*)&g_a[i1] = packh2(ofr[mi][j][2] * inv1, ofr[mi][j][3] * inv1);
        }
    }
}

// ---------------------------------------------------------------------------
// Launch. Inputs: x, mask, W_attn, b_attn, W_proj, b_proj.
// Output: [out (B,T,C) | k (B,H,T,D) | v (B,H,T,D)] fp32.
// ---------------------------------------------------------------------------
extern "C" void kernel_launch(void* const* d_in, const int* in_sizes, int n_in,
                              void* d_out, int out_size)
{
    (void)in_sizes; (void)n_in; (void)out_size;
    const float* x      = (const float*)d_in[0];
    const float* W_attn = (const float*)d_in[2];
    const float* b_attn = (const float*)d_in[3];
    const float* W_proj = (const float*)d_in[4];
    const float* b_proj = (const float*)d_in[5];

    float* out  = (float*)d_out;
    float* kout = out + (size_t)B_ * H_ * T_ * D_;
    float* vout = kout + (size_t)B_ * H_ * T_ * D_;

    cudaFuncSetAttribute(mma_gemm<0>, cudaFuncAttributeMaxDynamicSharedMemorySize,
                         SMEM_GEMM_BYTES);
    cudaFuncSetAttribute(mma_gemm<1>, cudaFuncAttributeMaxDynamicSharedMemorySize,
                         SMEM_GEMM_BYTES);
    cudaFuncSetAttribute(attn_mma, cudaFuncAttributeMaxDynamicSharedMemorySize,
                         AT_SMEM);

    // 1) fused conversions
    convert_all<<<5120, 256>>>(x, W_attn, W_proj);

    // 2) QKV GEMM + bias + scatter (tile 128x128 -> grid 24x64)
    mma_gemm<0><<<dim3(24, 64), 128, SMEM_GEMM_BYTES>>>(b_attn, nullptr, kout, vout);

    // 3) causal flash attention -> g_a
    attn_mma<<<dim3(16, 64), 128, AT_SMEM>>>();

    // 4) proj GEMM (grid 8x64)
    mma_gemm<1><<<dim3(8, 64), 128, SMEM_GEMM_BYTES>>>(b_proj, out, nullptr, nullptr);
}